// round 6
// baseline (speedup 1.0000x reference)
#include <cuda_runtime.h>
#include <math.h>

#define NPFX 100000
#define NOTH 200000
#define NEDG 500000
#define INDIM 512
#define DDIM  256

// ---------------- scratch (device globals; no allocation) ----------------
__device__ float    g_ssrc[NPFX];
__device__ float    g_sdst[NOTH];
__device__ float    g_e[NEDG];
__device__ float    g_ex[NEDG];
__device__ float    g_denom[NPFX];
__device__ unsigned g_mu[NPFX];
__device__ float    g_vp[DDIM];
__device__ float    g_vo[DDIM];
__device__ float    g_c[2];

// ordered-uint transform for float atomicMax (monotonic over all finite floats)
__device__ __forceinline__ unsigned enc_f(float x) {
    unsigned b = __float_as_uint(x);
    return (b & 0x80000000u) ? ~b : (b | 0x80000000u);
}
__device__ __forceinline__ float dec_f(unsigned u) {
    return (u & 0x80000000u) ? __uint_as_float(u ^ 0x80000000u)
                             : __uint_as_float(~u);
}

// ---------------- K1: fold W, bW, a_w into two vectors + two scalars ------
// s_src = hp @ (W @ a_w[:D]) + bW.a_w[:D];  s_dst likewise with a_w[D:]
__global__ void vecs_kernel(const float* __restrict__ W,
                            const float* __restrict__ bW,
                            const float* __restrict__ aw) {
    int k = threadIdx.x;  // 256 threads
    const float* wrow = W + (long)k * DDIM;
    float vp = 0.f, vo = 0.f;
    for (int j = 0; j < DDIM; j++) {
        float wv = wrow[j];
        vp = fmaf(wv, aw[j], vp);
        vo = fmaf(wv, aw[DDIM + j], vo);
    }
    g_vp[k] = vp;
    g_vo[k] = vo;

    __shared__ float r1[256], r2[256];
    r1[k] = bW[k] * aw[k];
    r2[k] = bW[k] * aw[DDIM + k];
    __syncthreads();
    for (int s = 128; s > 0; s >>= 1) {
        if (k < s) { r1[k] += r1[k + s]; r2[k] += r2[k + s]; }
        __syncthreads();
    }
    if (k == 0) { g_c[0] = r1[0]; g_c[1] = r2[0]; }
}

// ---------------- K2: init agg region of d_out + segment buffers ----------
__global__ void init_kernel(float* __restrict__ agg) {
    int i = blockIdx.x * blockDim.x + threadIdx.x;
    if (i < NPFX * DDIM) agg[i] = 0.f;
    if (i < NPFX) { g_mu[i] = 0u; g_denom[i] = 0.f; }
}

// ---------------- K3/K4: fused GEMM  C = relu(A @ Wm + b) -----------------
// Tile: BM=64 x BN=256 (full width) x BK=16; 256 threads, 8x8 per thread.
// Epilogue: optional store of C rows, and per-row dot with v (warp-reduced)
// to produce s (= segment score). which: 0 = prefix (g_vp/c0), 1 = other.
#define GBM 64
#define GBK 16

template <bool WRITE_C>
__global__ __launch_bounds__(256, 2)
void gemm_fused(const float* __restrict__ A, int M,
                const float* __restrict__ Bm,     // [512,256] row-major
                const float* __restrict__ bias,   // [256]
                int which,
                float* __restrict__ Cout) {       // [M,256] or unused
    __shared__ float As[GBK][GBM];
    __shared__ float Bs[GBK][DDIM];

    const int tid = threadIdx.x;
    const int w   = tid >> 5;      // warp 0..7 -> rows w*8..w*8+7
    const int l   = tid & 31;      // lane      -> cols l*4.. and 128+l*4..
    const int m0  = blockIdx.x * GBM;

    // A-tile loader mapping: row = tid/4, k-quad = (tid%4)*4
    const int arow = tid >> 2;
    const int akq  = (tid & 3) * 4;
    const bool arow_ok = (m0 + arow) < M;
    const float* Aptr = A + (long)(m0 + arow) * INDIM + akq;

    // B-tile loader mapping: n4 = (tid%64)*4, base k-row = tid/64 (+4 each)
    const int bn  = (tid & 63) * 4;
    const int bk0 = tid >> 6;

    float acc[8][8];
#pragma unroll
    for (int i = 0; i < 8; i++)
#pragma unroll
        for (int j = 0; j < 8; j++) acc[i][j] = 0.f;

    float4 av;
    float4 bv[4];
    // prefetch tile 0
    av = arow_ok ? *(const float4*)(Aptr) : make_float4(0.f, 0.f, 0.f, 0.f);
#pragma unroll
    for (int i = 0; i < 4; i++)
        bv[i] = *(const float4*)(Bm + (long)(bk0 + 4 * i) * DDIM + bn);

    for (int k0 = 0; k0 < INDIM; k0 += GBK) {
        __syncthreads();
        As[akq + 0][arow] = av.x;
        As[akq + 1][arow] = av.y;
        As[akq + 2][arow] = av.z;
        As[akq + 3][arow] = av.w;
#pragma unroll
        for (int i = 0; i < 4; i++)
            *(float4*)&Bs[bk0 + 4 * i][bn] = bv[i];
        __syncthreads();

        int kn = k0 + GBK;
        if (kn < INDIM) {  // prefetch next tile while computing this one
            av = arow_ok ? *(const float4*)(Aptr + kn)
                         : make_float4(0.f, 0.f, 0.f, 0.f);
#pragma unroll
            for (int i = 0; i < 4; i++)
                bv[i] = *(const float4*)(Bm + (long)(kn + bk0 + 4 * i) * DDIM + bn);
        }

#pragma unroll
        for (int kk = 0; kk < GBK; kk++) {
            float ra[8], rb[8];
            *(float4*)(ra)     = *(const float4*)&As[kk][w * 8];
            *(float4*)(ra + 4) = *(const float4*)&As[kk][w * 8 + 4];
            *(float4*)(rb)     = *(const float4*)&Bs[kk][l * 4];
            *(float4*)(rb + 4) = *(const float4*)&Bs[kk][128 + l * 4];
#pragma unroll
            for (int i = 0; i < 8; i++)
#pragma unroll
                for (int j = 0; j < 8; j++)
                    acc[i][j] = fmaf(ra[i], rb[j], acc[i][j]);
        }
    }

    // ---- epilogue: relu+bias, optional store, fused score dot ----
    const int c0 = l * 4, c1 = 128 + l * 4;
    const float4 ba = *(const float4*)&bias[c0];
    const float4 bb = *(const float4*)&bias[c1];
    const float* v  = which ? g_vo : g_vp;
    const float4 va = *(const float4*)&v[c0];
    const float4 vb = *(const float4*)&v[c1];
    const float cadd = g_c[which];
    float* sOut = which ? g_sdst : g_ssrc;

#pragma unroll
    for (int i = 0; i < 8; i++) {
        int row = m0 + w * 8 + i;    // warp-uniform
        if (row < M) {
            float4 oa, ob;
            oa.x = fmaxf(acc[i][0] + ba.x, 0.f);
            oa.y = fmaxf(acc[i][1] + ba.y, 0.f);
            oa.z = fmaxf(acc[i][2] + ba.z, 0.f);
            oa.w = fmaxf(acc[i][3] + ba.w, 0.f);
            ob.x = fmaxf(acc[i][4] + bb.x, 0.f);
            ob.y = fmaxf(acc[i][5] + bb.y, 0.f);
            ob.z = fmaxf(acc[i][6] + bb.z, 0.f);
            ob.w = fmaxf(acc[i][7] + bb.w, 0.f);

            float s = oa.x * va.x + oa.y * va.y + oa.z * va.z + oa.w * va.w +
                      ob.x * vb.x + ob.y * vb.y + ob.z * vb.z + ob.w * vb.w;
#pragma unroll
            for (int off = 16; off > 0; off >>= 1)
                s += __shfl_xor_sync(0xFFFFFFFFu, s, off);

            if (WRITE_C) {
                float* crow = Cout + (long)row * DDIM;
                *(float4*)(crow + c0) = oa;
                *(float4*)(crow + c1) = ob;
            }
            if (l == 0) sOut[row] = s + cadd;
        }
    }
}

// ---------------- K5: edge scores + segment max ---------------------------
__global__ void edge1_kernel(const int* __restrict__ src,
                             const int* __restrict__ dst,
                             const float* __restrict__ a_b) {
    int i = blockIdx.x * blockDim.x + threadIdx.x;
    if (i >= NEDG) return;
    int s = src[i];
    float ev = g_ssrc[s] + g_sdst[dst[i]] + a_b[0];
    g_e[i] = ev;
    atomicMax(&g_mu[s], enc_f(ev));
}

// ---------------- K6: exp + segment sum -----------------------------------
__global__ void edge2_kernel(const int* __restrict__ src) {
    int i = blockIdx.x * blockDim.x + threadIdx.x;
    if (i >= NEDG) return;
    int s = src[i];
    float x = expf(g_e[i] - dec_f(g_mu[s]));
    g_ex[i] = x;
    atomicAdd(&g_denom[s], x);
}

// ---------------- K7: scatter alpha * ho[dst] into agg[src] ---------------
// one warp per edge; 8 floats per lane
__global__ void scatter_kernel(const int* __restrict__ src,
                               const int* __restrict__ dst,
                               const float* __restrict__ ho,
                               float* __restrict__ agg) {
    int gw = (blockIdx.x * blockDim.x + threadIdx.x) >> 5;
    int l  = threadIdx.x & 31;
    if (gw >= NEDG) return;
    int s = src[gw], d = dst[gw];
    float alpha = g_ex[gw] / g_denom[s];
    const float4* hrow = (const float4*)(ho + (long)d * DDIM);
    float* arow = agg + (long)s * DDIM;
#pragma unroll
    for (int i = 0; i < 2; i++) {
        float4 hv = hrow[l + i * 32];
        int cb = (l + i * 32) * 4;
        atomicAdd(arow + cb + 0, alpha * hv.x);
        atomicAdd(arow + cb + 1, alpha * hv.y);
        atomicAdd(arow + cb + 2, alpha * hv.z);
        atomicAdd(arow + cb + 3, alpha * hv.w);
    }
}

// ---------------- K8: in-place row L2 normalize of all of d_out -----------
__global__ void norm_kernel(float* __restrict__ out, int nrows) {
    int gw = (blockIdx.x * blockDim.x + threadIdx.x) >> 5;
    int l  = threadIdx.x & 31;
    if (gw >= nrows) return;
    float4* row = (float4*)(out + (long)gw * DDIM);
    float4 a = row[l];
    float4 b = row[l + 32];
    float ss = a.x * a.x + a.y * a.y + a.z * a.z + a.w * a.w +
               b.x * b.x + b.y * b.y + b.z * b.z + b.w * b.w;
#pragma unroll
    for (int off = 16; off > 0; off >>= 1)
        ss += __shfl_xor_sync(0xFFFFFFFFu, ss, off);
    float sc = 1.0f / fmaxf(sqrtf(ss), 1e-12f);
    a.x *= sc; a.y *= sc; a.z *= sc; a.w *= sc;
    b.x *= sc; b.y *= sc; b.z *= sc; b.w *= sc;
    row[l]      = a;
    row[l + 32] = b;
}

// ---------------- launch ---------------------------------------------------
extern "C" void kernel_launch(void* const* d_in, const int* in_sizes, int n_in,
                              void* d_out, int out_size) {
    const float* feat_p = (const float*)d_in[0];
    const float* feat_o = (const float*)d_in[1];
    const int*   src    = (const int*)d_in[2];
    const int*   dst    = (const int*)d_in[3];
    const float* Wm_p   = (const float*)d_in[4];
    const float* bm_p   = (const float*)d_in[5];
    const float* Wm_o   = (const float*)d_in[6];
    const float* bm_o   = (const float*)d_in[7];
    const float* W      = (const float*)d_in[8];
    const float* bW     = (const float*)d_in[9];
    const float* a_w    = (const float*)d_in[10];
    const float* a_b    = (const float*)d_in[11];

    float* out = (float*)d_out;
    float* agg = out;                         // [NP, D] accumulator -> output 0
    float* ho  = out + (long)NPFX * DDIM;     // [NO, D] raw ho -> output 1

    vecs_kernel<<<1, 256>>>(W, bW, a_w);
    init_kernel<<<(NPFX * DDIM + 255) / 256, 256>>>(agg);

    // ho = relu(feat_other @ Wm_o + bm_o); also s_dst (fused)
    gemm_fused<true><<<(NOTH + GBM - 1) / GBM, 256>>>(
        feat_o, NOTH, Wm_o, bm_o, 1, ho);
    // s_src from relu(feat_prefix @ Wm_p + bm_p) . v_p  (hp never stored)
    gemm_fused<false><<<(NPFX + GBM - 1) / GBM, 256>>>(
        feat_p, NPFX, Wm_p, bm_p, 0, nullptr);

    edge1_kernel<<<(NEDG + 255) / 256, 256>>>(src, dst, a_b);
    edge2_kernel<<<(NEDG + 255) / 256, 256>>>(src);
    scatter_kernel<<<(NEDG + 7) / 8, 256>>>(src, dst, ho, agg);

    norm_kernel<<<((NPFX + NOTH) + 7) / 8, 256>>>(out, NPFX + NOTH);
}

// round 14
// speedup vs baseline: 1.5527x; 1.5527x over previous
#include <cuda_runtime.h>
#include <cuda_bf16.h>
#include <math.h>
#include <stdint.h>

#define NPFX 100000
#define NOTH 200000
#define NEDG 500000
#define INDIM 512
#define DDIM  256

// ---------------- scratch (device globals; no allocation) ----------------
__device__ float    g_ssrc[NPFX];
__device__ float    g_sdst[NOTH];
__device__ float    g_e[NEDG];
__device__ float    g_ex[NEDG];
__device__ float    g_denom[NPFX];
__device__ unsigned g_mu[NPFX];
__device__ float    g_vp[DDIM];
__device__ float    g_vo[DDIM];
__device__ float    g_c[2];
// pre-transposed bf16 hi/lo copies of Wm_p / Wm_o, layout [n][k] (k fastest)
__device__ __align__(16) __nv_bfloat16 g_Bh[2][DDIM * INDIM];
__device__ __align__(16) __nv_bfloat16 g_Bl[2][DDIM * INDIM];

// ordered-uint transform for float atomicMax
__device__ __forceinline__ unsigned enc_f(float x) {
    unsigned b = __float_as_uint(x);
    return (b & 0x80000000u) ? ~b : (b | 0x80000000u);
}
__device__ __forceinline__ float dec_f(unsigned u) {
    return (u & 0x80000000u) ? __uint_as_float(u ^ 0x80000000u)
                             : __uint_as_float(~u);
}

// ---------------- baseline-PTX tensor helpers (sm_80-era, safe) -----------
__device__ __forceinline__ void ldm4(uint32_t* r, uint32_t addr) {
    asm volatile("ldmatrix.sync.aligned.m8n8.x4.shared.b16 {%0,%1,%2,%3}, [%4];"
                 : "=r"(r[0]), "=r"(r[1]), "=r"(r[2]), "=r"(r[3]) : "r"(addr));
}
__device__ __forceinline__ void mma16816(float* d, const uint32_t* a,
                                         uint32_t b0, uint32_t b1) {
    asm volatile(
        "mma.sync.aligned.m16n8k16.row.col.f32.bf16.bf16.f32 "
        "{%0,%1,%2,%3}, {%4,%5,%6,%7}, {%8,%9}, {%0,%1,%2,%3};"
        : "+f"(d[0]), "+f"(d[1]), "+f"(d[2]), "+f"(d[3])
        : "r"(a[0]), "r"(a[1]), "r"(a[2]), "r"(a[3]), "r"(b0), "r"(b1));
}
__device__ __forceinline__ void cpa16(uint32_t dst, const void* src) {
    asm volatile("cp.async.cg.shared.global [%0], [%1], 16;" :: "r"(dst), "l"(src));
}
__device__ __forceinline__ void cpa_commit() {
    asm volatile("cp.async.commit_group;");
}
__device__ __forceinline__ void cpa_wait0() {
    asm volatile("cp.async.wait_group 0;");
}

// ---------------- K1: fold W, bW, a_w into two vectors + two scalars ------
__global__ void vecs_kernel(const float* __restrict__ W,
                            const float* __restrict__ bW,
                            const float* __restrict__ aw) {
    int k = threadIdx.x;  // 256 threads
    const float* wrow = W + (long)k * DDIM;
    float vp = 0.f, vo = 0.f;
    for (int j = 0; j < DDIM; j++) {
        float wv = wrow[j];
        vp = fmaf(wv, aw[j], vp);
        vo = fmaf(wv, aw[DDIM + j], vo);
    }
    g_vp[k] = vp;
    g_vo[k] = vo;

    __shared__ float r1[256], r2[256];
    r1[k] = bW[k] * aw[k];
    r2[k] = bW[k] * aw[DDIM + k];
    __syncthreads();
    for (int s = 128; s > 0; s >>= 1) {
        if (k < s) { r1[k] += r1[k + s]; r2[k] += r2[k + s]; }
        __syncthreads();
    }
    if (k == 0) { g_c[0] = r1[0]; g_c[1] = r2[0]; }
}

// ---------------- K2: init agg region of d_out + segment buffers ----------
__global__ void init_kernel(float* __restrict__ agg) {
    int i = blockIdx.x * blockDim.x + threadIdx.x;
    if (i < NPFX * DDIM) agg[i] = 0.f;
    if (i < NPFX) { g_mu[i] = 0u; g_denom[i] = 0.f; }
}

// ---------------- K2b: transpose + split Wm -> bf16 hi/lo [n][k] ----------
__global__ void convB_kernel(const float* __restrict__ Wm0,
                             const float* __restrict__ Wm1) {
    int idx = blockIdx.x * blockDim.x + threadIdx.x;  // 32768 threads
    int which = idx >> 14;
    int rem = idx & 16383;
    int n  = rem & 255;
    int ko = rem >> 8;   // 0..63 (8 k-elems each)
    const float* Wm = which ? Wm1 : Wm0;
    unsigned hw[8], lw[8];
#pragma unroll
    for (int j = 0; j < 8; j++) {
        float x = Wm[(size_t)(ko * 8 + j) * DDIM + n];
        __nv_bfloat16 h = __float2bfloat16_rn(x);
        __nv_bfloat16 l = __float2bfloat16_rn(x - __bfloat162float(h));
        hw[j] = __bfloat16_as_ushort(h);
        lw[j] = __bfloat16_as_ushort(l);
    }
    uint4 vh = make_uint4(hw[0] | (hw[1] << 16), hw[2] | (hw[3] << 16),
                          hw[4] | (hw[5] << 16), hw[6] | (hw[7] << 16));
    uint4 vl = make_uint4(lw[0] | (lw[1] << 16), lw[2] | (lw[3] << 16),
                          lw[4] | (lw[5] << 16), lw[6] | (lw[7] << 16));
    *(uint4*)&g_Bh[which][(size_t)n * INDIM + ko * 8] = vh;
    *(uint4*)&g_Bl[which][(size_t)n * INDIM + ko * 8] = vl;
}

// ---------------- K3/K4: mma.sync bf16-split GEMM  C = relu(A@Wm + b) -----
// CTA tile 128(M) x 256(N), K-chunk 64, 512 threads = 16 warps (4M x 4N),
// warp tile m32n64. Padded SMEM rows (144B) -> conflict-free ldmatrix.
#define ASTR    144
#define AH_OFF  0
#define AL_OFF  18432            // 128 * 144
#define BH_OFF  36864
#define BL_OFF  73728            // BH + 256*144
#define STAGE   110592           // BL + 256*144
#define SMEM_DYN (2 * STAGE)     // 221184 bytes

template <bool WRITE_C>
__global__ __launch_bounds__(512)
void mma_gemm(const float* __restrict__ A, int M, int which,
              const float* __restrict__ bias, float* __restrict__ Cout) {
    extern __shared__ char dsm[];
    const uint32_t base_u = (uint32_t)__cvta_generic_to_shared(dsm);

    const int tid = threadIdx.x;
    const int wid = tid >> 5, lid = tid & 31;
    const int wm  = wid >> 2, wn  = wid & 3;     // warp grid 4(M) x 4(N)
    const int g   = lid >> 2, tig = lid & 3;
    const int m0  = blockIdx.x * 128;

    // --- loader: A fp32 -> bf16 hi/lo in SMEM (rows padded to 144B) ---
    const int arow = tid >> 2;            // 0..127
    const int akq  = (tid & 3) * 16;      // k offset (elements)
    auto loadA = [&](int k0, int buf) {
        if (m0 + arow < M) {
            const float* p = A + (size_t)(m0 + arow) * INDIM + k0 + akq;
            float f[16];
#pragma unroll
            for (int q = 0; q < 4; q++)
                *(float4*)(f + q * 4) = *(const float4*)(p + q * 4);
            unsigned hi[8], lo[8];
#pragma unroll
            for (int j = 0; j < 8; j++) {
                float a = f[2 * j], b = f[2 * j + 1];
                __nv_bfloat16 ha = __float2bfloat16_rn(a);
                __nv_bfloat16 hb = __float2bfloat16_rn(b);
                __nv_bfloat16 la = __float2bfloat16_rn(a - __bfloat162float(ha));
                __nv_bfloat16 lb = __float2bfloat16_rn(b - __bfloat162float(hb));
                hi[j] = __bfloat16_as_ushort(ha) | ((unsigned)__bfloat16_as_ushort(hb) << 16);
                lo[j] = __bfloat16_as_ushort(la) | ((unsigned)__bfloat16_as_ushort(lb) << 16);
            }
            char* sb = dsm + buf * STAGE + arow * ASTR + akq * 2;
            *(uint4*)(sb + AH_OFF)      = make_uint4(hi[0], hi[1], hi[2], hi[3]);
            *(uint4*)(sb + AH_OFF + 16) = make_uint4(hi[4], hi[5], hi[6], hi[7]);
            *(uint4*)(sb + AL_OFF)      = make_uint4(lo[0], lo[1], lo[2], lo[3]);
            *(uint4*)(sb + AL_OFF + 16) = make_uint4(lo[4], lo[5], lo[6], lo[7]);
        }
    };
    // --- loader: B bf16 hi/lo via cp.async (8 x 16B per thread) ---
    const __nv_bfloat16* Bh = g_Bh[which];
    const __nv_bfloat16* Bl = g_Bl[which];
    auto loadB = [&](int k0, int buf) {
        uint32_t sb = base_u + buf * STAGE;
#pragma unroll
        for (int i = 0; i < 8; i++) {
            int seg = tid + i * 512;
            int hl  = seg >> 11;          // 0 = hi, 1 = lo
            int s   = seg & 2047;
            int row = s >> 3, s8 = s & 7;
            const __nv_bfloat16* src =
                (hl ? Bl : Bh) + (size_t)row * INDIM + k0 + s8 * 8;
            cpa16(sb + (hl ? BL_OFF : BH_OFF) + row * ASTR + s8 * 16, src);
        }
    };

    float acc[2][8][4];
#pragma unroll
    for (int mt = 0; mt < 2; mt++)
#pragma unroll
        for (int nt = 0; nt < 8; nt++)
#pragma unroll
            for (int q = 0; q < 4; q++) acc[mt][nt][q] = 0.f;

    // per-lane ldmatrix address invariants
    const uint32_t a_lane = (uint32_t)((wm * 32 + (lid & 15)) * ASTR + (lid >> 4) * 16);
    const uint32_t b_lane = (uint32_t)((wn * 64 + (lid & 7) + ((lid >> 4) & 1) * 8) * ASTR
                                       + ((lid >> 3) & 1) * 16);

    loadB(0, 0); cpa_commit();
    loadA(0, 0);

    for (int c = 0; c < INDIM / 64; c++) {
        cpa_wait0();
        __syncthreads();
        if (c + 1 < INDIM / 64) {
            loadB((c + 1) * 64, (c + 1) & 1); cpa_commit();
            loadA((c + 1) * 64, (c + 1) & 1);
        }
        uint32_t sb = base_u + (c & 1) * STAGE;
#pragma unroll
        for (int ks = 0; ks < 4; ks++) {
            uint32_t ah[2][4], al[2][4], bb[4][4];
            uint32_t ab = sb + AH_OFF + a_lane + ks * 32;
            ldm4(ah[0], ab);
            ldm4(ah[1], ab + 16 * ASTR);
            ldm4(al[0], ab + (AL_OFF - AH_OFF));
            ldm4(al[1], ab + (AL_OFF - AH_OFF) + 16 * ASTR);
            uint32_t bbse = sb + BH_OFF + b_lane + ks * 32;
#pragma unroll
            for (int t = 0; t < 4; t++) ldm4(bb[t], bbse + t * 16 * ASTR);
#pragma unroll
            for (int nt = 0; nt < 8; nt++) {
                uint32_t b0 = bb[nt >> 1][(nt & 1) * 2];
                uint32_t b1 = bb[nt >> 1][(nt & 1) * 2 + 1];
                mma16816(acc[0][nt], ah[0], b0, b1);
                mma16816(acc[1][nt], ah[1], b0, b1);
                mma16816(acc[0][nt], al[0], b0, b1);
                mma16816(acc[1][nt], al[1], b0, b1);
            }
            uint32_t blse = sb + BL_OFF + b_lane + ks * 32;
#pragma unroll
            for (int t = 0; t < 4; t++) ldm4(bb[t], blse + t * 16 * ASTR);
#pragma unroll
            for (int nt = 0; nt < 8; nt++) {
                uint32_t b0 = bb[nt >> 1][(nt & 1) * 2];
                uint32_t b1 = bb[nt >> 1][(nt & 1) * 2 + 1];
                mma16816(acc[0][nt], ah[0], b0, b1);
                mma16816(acc[1][nt], ah[1], b0, b1);
            }
        }
    }

    // ---- epilogue: bias+relu, score partials, optional C store ----
    const float* v = which ? g_vo : g_vp;
    float p[4] = {0.f, 0.f, 0.f, 0.f};
#pragma unroll
    for (int mt = 0; mt < 2; mt++) {
#pragma unroll
        for (int nt = 0; nt < 8; nt++) {
            int col = wn * 64 + nt * 8 + tig * 2;
            float b0v = bias[col], b1v = bias[col + 1];
            float v0 = v[col], v1 = v[col + 1];
            float* a4 = acc[mt][nt];
            float o0 = fmaxf(a4[0] + b0v, 0.f), o1 = fmaxf(a4[1] + b1v, 0.f);
            float o2 = fmaxf(a4[2] + b0v, 0.f), o3 = fmaxf(a4[3] + b1v, 0.f);
            p[mt * 2]     += o0 * v0 + o1 * v1;
            p[mt * 2 + 1] += o2 * v0 + o3 * v1;
            if (WRITE_C) {
                int r0 = m0 + wm * 32 + mt * 16 + g;
                if (r0 < M)
                    *(float2*)(Cout + (size_t)r0 * DDIM + col) = make_float2(o0, o1);
                if (r0 + 8 < M)
                    *(float2*)(Cout + (size_t)(r0 + 8) * DDIM + col) = make_float2(o2, o3);
            }
        }
    }
    // reduce over tig quad (lanes g*4 + {0..3})
#pragma unroll
    for (int i = 0; i < 4; i++) {
        p[i] += __shfl_xor_sync(0xFFFFFFFFu, p[i], 1);
        p[i] += __shfl_xor_sync(0xFFFFFFFFu, p[i], 2);
    }
    float* sp = (float*)dsm;  // stage0 Ah region; unused by last chunk (buf 1)
    if (tig == 0) {
#pragma unroll
        for (int i = 0; i < 4; i++) {
            int row_l = wm * 32 + (i >> 1) * 16 + (i & 1) * 8 + g;
            sp[row_l * 4 + wn] = p[i];
        }
    }
    __syncthreads();
    if (tid < 128 && m0 + tid < M) {
        float s = sp[tid * 4] + sp[tid * 4 + 1] + sp[tid * 4 + 2] + sp[tid * 4 + 3];
        (which ? g_sdst : g_ssrc)[m0 + tid] = s + g_c[which];
    }
}

// ---------------- K5: edge scores + segment max ---------------------------
__global__ void edge1_kernel(const int* __restrict__ src,
                             const int* __restrict__ dst,
                             const float* __restrict__ a_b) {
    int i = blockIdx.x * blockDim.x + threadIdx.x;
    if (i >= NEDG) return;
    int s = src[i];
    float ev = g_ssrc[s] + g_sdst[dst[i]] + a_b[0];
    g_e[i] = ev;
    atomicMax(&g_mu[s], enc_f(ev));
}

// ---------------- K6: exp + segment sum -----------------------------------
__global__ void edge2_kernel(const int* __restrict__ src) {
    int i = blockIdx.x * blockDim.x + threadIdx.x;
    if (i >= NEDG) return;
    int s = src[i];
    float x = expf(g_e[i] - dec_f(g_mu[s]));
    g_ex[i] = x;
    atomicAdd(&g_denom[s], x);
}

// ---------------- K7: scatter alpha * ho[dst] into agg[src] ---------------
__global__ void scatter_kernel(const int* __restrict__ src,
                               const int* __restrict__ dst,
                               const float* __restrict__ ho,
                               float* __restrict__ agg) {
    int gw = (blockIdx.x * blockDim.x + threadIdx.x) >> 5;
    int l  = threadIdx.x & 31;
    if (gw >= NEDG) return;
    int s = src[gw], d = dst[gw];
    float alpha = g_ex[gw] / g_denom[s];
    const float4* hrow = (const float4*)(ho + (long)d * DDIM);
    float* arow = agg + (long)s * DDIM;
#pragma unroll
    for (int i = 0; i < 2; i++) {
        float4 hv = hrow[l + i * 32];
        int cb = (l + i * 32) * 4;
        atomicAdd(arow + cb + 0, alpha * hv.x);
        atomicAdd(arow + cb + 1, alpha * hv.y);
        atomicAdd(arow + cb + 2, alpha * hv.z);
        atomicAdd(arow + cb + 3, alpha * hv.w);
    }
}

// ---------------- K8: in-place row L2 normalize of all of d_out -----------
__global__ void norm_kernel(float* __restrict__ out, int nrows) {
    int gw = (blockIdx.x * blockDim.x + threadIdx.x) >> 5;
    int l  = threadIdx.x & 31;
    if (gw >= nrows) return;
    float4* row = (float4*)(out + (long)gw * DDIM);
    float4 a = row[l];
    float4 b = row[l + 32];
    float ss = a.x * a.x + a.y * a.y + a.z * a.z + a.w * a.w +
               b.x * b.x + b.y * b.y + b.z * b.z + b.w * b.w;
#pragma unroll
    for (int off = 16; off > 0; off >>= 1)
        ss += __shfl_xor_sync(0xFFFFFFFFu, ss, off);
    float sc = 1.0f / fmaxf(sqrtf(ss), 1e-12f);
    a.x *= sc; a.y *= sc; a.z *= sc; a.w *= sc;
    b.x *= sc; b.y *= sc; b.z *= sc; b.w *= sc;
    row[l]      = a;
    row[l + 32] = b;
}

// ---------------- launch ---------------------------------------------------
extern "C" void kernel_launch(void* const* d_in, const int* in_sizes, int n_in,
                              void* d_out, int out_size) {
    const float* feat_p = (const float*)d_in[0];
    const float* feat_o = (const float*)d_in[1];
    const int*   src    = (const int*)d_in[2];
    const int*   dst    = (const int*)d_in[3];
    const float* Wm_p   = (const float*)d_in[4];
    const float* bm_p   = (const float*)d_in[5];
    const float* Wm_o   = (const float*)d_in[6];
    const float* bm_o   = (const float*)d_in[7];
    const float* W      = (const float*)d_in[8];
    const float* bW     = (const float*)d_in[9];
    const float* a_w    = (const float*)d_in[10];
    const float* a_b    = (const float*)d_in[11];

    float* out = (float*)d_out;
    float* agg = out;                         // [NP, D] accumulator -> output 0
    float* ho  = out + (long)NPFX * DDIM;     // [NO, D] raw ho -> output 1

    cudaFuncSetAttribute(mma_gemm<true>,
                         cudaFuncAttributeMaxDynamicSharedMemorySize, SMEM_DYN);
    cudaFuncSetAttribute(mma_gemm<false>,
                         cudaFuncAttributeMaxDynamicSharedMemorySize, SMEM_DYN);

    vecs_kernel<<<1, 256>>>(W, bW, a_w);
    init_kernel<<<(NPFX * DDIM + 255) / 256, 256>>>(agg);
    convB_kernel<<<128, 256>>>(Wm_p, Wm_o);

    mma_gemm<true><<<(NOTH + 127) / 128, 512, SMEM_DYN>>>(feat_o, NOTH, 1, bm_o, ho);
    mma_gemm<false><<<(NPFX + 127) / 128, 512, SMEM_DYN>>>(feat_p, NPFX, 0, bm_p, nullptr);

    edge1_kernel<<<(NEDG + 255) / 256, 256>>>(src, dst, a_b);
    edge2_kernel<<<(NEDG + 255) / 256, 256>>>(src);
    scatter_kernel<<<(NEDG + 7) / 8, 256>>>(src, dst, ho, agg);

    norm_kernel<<<((NPFX + NOTH) + 7) / 8, 256>>>(out, NPFX + NOTH);
}